// round 2
// baseline (speedup 1.0000x reference)
#include <cuda_runtime.h>
#include <cuda_bf16.h>
#include <cstdint>

// if_encoder: integrate-and-fire with soft reset (bit-exact vs reference scan).
//   d_in[0] input_spikes [B=64, D=4096, T=128] f32 (T contiguous)
//   d_in[1] states       [B, D] f32
//   d_in[2] threshold    scalar f32
//   d_out  = spikes [B, D, T] f32  followed by  v_final [B, D] f32
//
// One thread per (b,d) row. Input staged into shared memory with cp.async.cg
// (no load registers -> high occupancy), scan runs on float4 smem accesses
// (stride-36 rows: every 128-bit LDS/STS is bank-conflict-free), spikes
// written back through smem with coalesced STG.128.

static constexpr int B_ = 64;
static constexpr int D_ = 4096;
static constexpr int T_ = 128;
static constexpr long long ROWS = (long long)B_ * D_;   // 262144
static constexpr int BLOCK = 256;
static constexpr int TT = 32;                           // time-tile (floats)
static constexpr int TILES = T_ / TT;                   // 4
static constexpr int SROW = TT + 4;                     // 36 floats = 144B: 16B-aligned + conflict-free f4

__device__ __forceinline__ void cp_async16(uint32_t smem_addr, const void* gptr) {
    asm volatile("cp.async.cg.shared.global [%0], [%1], 16;\n"
                 :: "r"(smem_addr), "l"(gptr) : "memory");
}
__device__ __forceinline__ void cp_async_commit_wait() {
    asm volatile("cp.async.commit_group;\n" ::: "memory");
    asm volatile("cp.async.wait_group 0;\n" ::: "memory");
}

__global__ __launch_bounds__(BLOCK, 6)
void if_encoder_kernel(const float* __restrict__ x,
                       const float* __restrict__ states,
                       const float* __restrict__ thr_ptr,
                       float* __restrict__ spikes,
                       float* __restrict__ vfinal,
                       int write_vfinal) {
    __shared__ __align__(16) float s[BLOCK * SROW];   // 36864 B

    const int tid = threadIdx.x;
    const long long row0 = (long long)blockIdx.x * BLOCK;
    const long long row  = row0 + tid;

    const float thr = thr_ptr[0];
    float v = states[row];

    const float4* __restrict__ x4  = reinterpret_cast<const float4*>(x);
    float4* __restrict__       sp4 = reinterpret_cast<float4*>(spikes);

    const uint32_t s_base = (uint32_t)__cvta_generic_to_shared(s);
    float* const my = &s[tid * SROW];

    #pragma unroll
    for (int tile = 0; tile < TILES; ++tile) {
        const int c4base = tile * (TT / 4);   // float4 column base within row

        // ---- async coalesced load: 2048 x 16B per block, 8 per thread ----
        #pragma unroll
        for (int k = 0; k < 8; ++k) {
            const int e  = k * BLOCK + tid;   // 0..2047
            const int r  = e >> 3;            // row within block (8 lanes share)
            const int c4 = e & 7;             // float4 col within tile
            const uint32_t dst = s_base + (uint32_t)(r * SROW + c4 * 4) * 4u;
            cp_async16(dst, &x4[(row0 + r) * (T_ / 4) + c4base + c4]);
        }
        cp_async_commit_wait();
        __syncthreads();

        // ---- sequential scan: float4 in, float4 spikes out (conflict-free) ----
        #pragma unroll
        for (int c4 = 0; c4 < TT / 4; ++c4) {
            const float4 xx = *reinterpret_cast<const float4*>(my + 4 * c4);
            float4 sp;
            v += xx.x; sp.x = (v >= thr) ? 1.0f : 0.0f; v = fmaf(-sp.x, thr, v);
            v += xx.y; sp.y = (v >= thr) ? 1.0f : 0.0f; v = fmaf(-sp.y, thr, v);
            v += xx.z; sp.z = (v >= thr) ? 1.0f : 0.0f; v = fmaf(-sp.z, thr, v);
            v += xx.w; sp.w = (v >= thr) ? 1.0f : 0.0f; v = fmaf(-sp.w, thr, v);
            *reinterpret_cast<float4*>(my + 4 * c4) = sp;
        }
        __syncthreads();

        // ---- coalesced store of spikes (LDS.128 -> STG.128) ----
        #pragma unroll
        for (int k = 0; k < 8; ++k) {
            const int e  = k * BLOCK + tid;
            const int r  = e >> 3;
            const int c4 = e & 7;
            const float4 f = *reinterpret_cast<const float4*>(&s[r * SROW + c4 * 4]);
            sp4[(row0 + r) * (T_ / 4) + c4base + c4] = f;
        }
        __syncthreads();   // protect smem before next tile's cp.async overwrites
    }

    if (write_vfinal) {
        vfinal[row] = v;
    }
}

extern "C" void kernel_launch(void* const* d_in, const int* in_sizes, int n_in,
                              void* d_out, int out_size) {
    const float* x      = (const float*)d_in[0];
    const float* states = (const float*)d_in[1];
    const float* thr    = (const float*)d_in[2];

    float* out    = (float*)d_out;
    float* spikes = out;
    float* vfin   = out + ROWS * T_;

    const long long need = ROWS * T_ + ROWS;
    const int write_vfinal = ((long long)out_size >= need) ? 1 : 0;

    const int grid = (int)(ROWS / BLOCK);   // 1024
    if_encoder_kernel<<<grid, BLOCK>>>(x, states, thr, spikes, vfin, write_vfinal);
}

// round 3
// speedup vs baseline: 1.4570x; 1.4570x over previous
#include <cuda_runtime.h>
#include <cuda_bf16.h>
#include <cstdint>

// if_encoder: integrate-and-fire with soft reset (bit-exact vs reference scan).
//   d_in[0] input_spikes [B=64, D=4096, T=128] f32 (T contiguous)
//   d_in[1] states       [B, D] f32
//   d_in[2] threshold    scalar f32
//   d_out  = spikes [B, D, T] f32  followed by  v_final [B, D] f32
//
// One thread per (b,d) row. Double-buffered cp.async pipeline: tile t+1 is
// always in flight while tile t is scanned/stored, keeping DRAM reads
// outstanding 100% of the time. XOR-swizzled smem (no padding) makes every
// 128-bit LDS/STS conflict-free; buffers are exactly 32KB each.

static constexpr int B_ = 64;
static constexpr int D_ = 4096;
static constexpr int T_ = 128;
static constexpr long long ROWS = (long long)B_ * D_;   // 262144
static constexpr int BLOCK = 256;
static constexpr int TT = 32;                           // time-tile (floats)
static constexpr int TILES = T_ / TT;                   // 4
static constexpr int C4 = TT / 4;                       // 8 float4 per row-tile

__device__ __forceinline__ void cp_async16(uint32_t smem_addr, const void* gptr) {
    asm volatile("cp.async.cg.shared.global [%0], [%1], 16;\n"
                 :: "r"(smem_addr), "l"(gptr) : "memory");
}
__device__ __forceinline__ void cp_commit() {
    asm volatile("cp.async.commit_group;\n" ::: "memory");
}
template <int N>
__device__ __forceinline__ void cp_wait() {
    asm volatile("cp.async.wait_group %0;\n" :: "n"(N) : "memory");
}

__global__ __launch_bounds__(BLOCK)
void if_encoder_kernel(const float* __restrict__ x,
                       const float* __restrict__ states,
                       const float* __restrict__ thr_ptr,
                       float* __restrict__ spikes,
                       float* __restrict__ vfinal,
                       int write_vfinal) {
    // [2 buffers][256 rows][8 float4 slots], XOR-swizzled: 65536 B
    __shared__ __align__(16) float4 buf[2][BLOCK][C4];

    const int tid = threadIdx.x;
    const long long row0 = (long long)blockIdx.x * BLOCK;
    const long long row  = row0 + tid;

    const float4* __restrict__ x4  = reinterpret_cast<const float4*>(x);
    float4* __restrict__       sp4 = reinterpret_cast<float4*>(spikes);

    const uint32_t s_base = (uint32_t)__cvta_generic_to_shared(&buf[0][0][0]);

    // ---- issue loads for tile 0 immediately ----
    {
        #pragma unroll
        for (int k = 0; k < 8; ++k) {
            const int e  = k * BLOCK + tid;
            const int r  = e >> 3;
            const int c4 = e & 7;
            const int slot = c4 ^ (r & 7);
            const uint32_t dst = s_base + (uint32_t)((0 * BLOCK + r) * C4 + slot) * 16u;
            cp_async16(dst, &x4[(row0 + r) * (T_ / 4) + c4]);
        }
        cp_commit();
    }

    const float thr = thr_ptr[0];
    float v = states[row];

    const int myswz = tid & 7;

    #pragma unroll
    for (int tile = 0; tile < TILES; ++tile) {
        const int b = tile & 1;
        const int c4base = tile * C4;

        // ---- issue loads for tile+1 into the other buffer (its previous
        //      contents were fully stored before last iteration's barrier) ----
        if (tile + 1 < TILES) {
            const int nb = (tile + 1) & 1;
            #pragma unroll
            for (int k = 0; k < 8; ++k) {
                const int e  = k * BLOCK + tid;
                const int r  = e >> 3;
                const int c4 = e & 7;
                const int slot = c4 ^ (r & 7);
                const uint32_t dst = s_base + (uint32_t)((nb * BLOCK + r) * C4 + slot) * 16u;
                cp_async16(dst, &x4[(row0 + r) * (T_ / 4) + c4base + C4 + c4]);
            }
            cp_commit();
            cp_wait<1>();   // tile's own data is ready; tile+1 stays in flight
        } else {
            cp_wait<0>();
        }
        __syncthreads();

        // ---- sequential scan of this thread's row (swizzled, conflict-free) ----
        float4* const my = &buf[b][tid][0];
        #pragma unroll
        for (int c4 = 0; c4 < C4; ++c4) {
            float4* const p = &my[c4 ^ myswz];
            const float4 xx = *p;
            float4 sp;
            v += xx.x; sp.x = (v >= thr) ? 1.0f : 0.0f; v = fmaf(-sp.x, thr, v);
            v += xx.y; sp.y = (v >= thr) ? 1.0f : 0.0f; v = fmaf(-sp.y, thr, v);
            v += xx.z; sp.z = (v >= thr) ? 1.0f : 0.0f; v = fmaf(-sp.z, thr, v);
            v += xx.w; sp.w = (v >= thr) ? 1.0f : 0.0f; v = fmaf(-sp.w, thr, v);
            *p = sp;
        }
        __syncthreads();

        // ---- coalesced streaming store of spikes ----
        #pragma unroll
        for (int k = 0; k < 8; ++k) {
            const int e  = k * BLOCK + tid;
            const int r  = e >> 3;
            const int c4 = e & 7;
            const int slot = c4 ^ (r & 7);
            const float4 f = buf[b][r][slot];
            __stcs(&sp4[(row0 + r) * (T_ / 4) + c4base + c4], f);
        }
        __syncthreads();   // buffer b fully drained before it is reloaded
    }

    if (write_vfinal) {
        vfinal[row] = v;
    }
}

extern "C" void kernel_launch(void* const* d_in, const int* in_sizes, int n_in,
                              void* d_out, int out_size) {
    const float* x      = (const float*)d_in[0];
    const float* states = (const float*)d_in[1];
    const float* thr    = (const float*)d_in[2];

    float* out    = (float*)d_out;
    float* spikes = out;
    float* vfin   = out + ROWS * T_;

    const long long need = ROWS * T_ + ROWS;
    const int write_vfinal = ((long long)out_size >= need) ? 1 : 0;

    const int grid = (int)(ROWS / BLOCK);   // 1024
    if_encoder_kernel<<<grid, BLOCK>>>(x, states, thr, spikes, vfin, write_vfinal);
}

// round 4
// speedup vs baseline: 1.4659x; 1.0061x over previous
#include <cuda_runtime.h>
#include <cuda_bf16.h>
#include <cstdint>

// if_encoder: integrate-and-fire with soft reset (bit-exact vs reference scan).
//   d_in[0] input_spikes [B=64, D=4096, T=128] f32 (T contiguous)
//   d_in[1] states       [B, D] f32
//   d_in[2] threshold    scalar f32
//   d_out  = spikes [B, D, T] f32  followed by  v_final [B, D] f32
//
// One thread per (b,d) row. 3-stage cp.async pipeline (prefetch depth 2):
// two 16KB tiles are always in flight per block, 4 blocks/SM -> up to 128KB
// of reads outstanding per SM, keeping the DRAM read stream busy through the
// scan/store phases. XOR-swizzled smem keeps every 128-bit LDS/STS
// conflict-free in all three phases.

static constexpr int B_ = 64;
static constexpr int D_ = 4096;
static constexpr int T_ = 128;
static constexpr long long ROWS = (long long)B_ * D_;   // 262144
static constexpr int BLOCK = 256;
static constexpr int TT = 16;                           // time-tile (floats)
static constexpr int TILES = T_ / TT;                   // 8
static constexpr int C4 = TT / 4;                       // 4 float4 per row-tile
static constexpr int NBUF = 3;

__device__ __forceinline__ void cp_async16(uint32_t smem_addr, const void* gptr) {
    asm volatile("cp.async.cg.shared.global [%0], [%1], 16;\n"
                 :: "r"(smem_addr), "l"(gptr) : "memory");
}
__device__ __forceinline__ void cp_commit() {
    asm volatile("cp.async.commit_group;\n" ::: "memory");
}
template <int N>
__device__ __forceinline__ void cp_wait() {
    asm volatile("cp.async.wait_group %0;\n" :: "n"(N) : "memory");
}

// swizzled float4-slot within a row: conflict-free for scan (lane==row) and
// load/store (4 lanes per row) phases at quarter-warp granularity.
__device__ __forceinline__ int swz(int r, int c4) { return c4 ^ ((r >> 1) & 3); }

__global__ __launch_bounds__(BLOCK, 4)
void if_encoder_kernel(const float* __restrict__ x,
                       const float* __restrict__ states,
                       const float* __restrict__ thr_ptr,
                       float* __restrict__ spikes,
                       float* __restrict__ vfinal,
                       int write_vfinal) {
    __shared__ __align__(16) float4 buf[NBUF][BLOCK][C4];   // 3 x 16KB

    const int tid = threadIdx.x;
    const long long row0 = (long long)blockIdx.x * BLOCK;
    const long long row  = row0 + tid;

    const float4* __restrict__ x4  = reinterpret_cast<const float4*>(x);
    float4* __restrict__       sp4 = reinterpret_cast<float4*>(spikes);

    const uint32_t s_base = (uint32_t)__cvta_generic_to_shared(&buf[0][0][0]);

    // this thread's fixed (r, c4) for the load/store phases: 4 elems per tile
    const int lr  = tid >> 2;          // base row for k=0 chunk
    const int lc4 = tid & 3;

    // ---- prologue: issue tiles 0 and 1 ----
    #pragma unroll
    for (int t = 0; t < 2; ++t) {
        #pragma unroll
        for (int k = 0; k < 4; ++k) {
            const int r  = lr + k * (BLOCK / 4);
            const uint32_t dst = s_base +
                (uint32_t)(((t * BLOCK + r) * C4 + swz(r, lc4)) * 16);
            cp_async16(dst, &x4[(row0 + r) * (T_ / 4) + t * C4 + lc4]);
        }
        cp_commit();
    }

    const float thr = thr_ptr[0];
    float v = states[row];

    const int myswz = (tid >> 1) & 3;

    #pragma unroll
    for (int tile = 0; tile < TILES; ++tile) {
        const int b = tile % NBUF;

        // ---- issue loads for tile+2 (buffer freed by the barrier that ended
        //      iteration tile-1, which followed the store of tile-1) ----
        if (tile + 2 < TILES) {
            const int nb = (tile + 2) % NBUF;
            const int nc4base = (tile + 2) * C4;
            #pragma unroll
            for (int k = 0; k < 4; ++k) {
                const int r  = lr + k * (BLOCK / 4);
                const uint32_t dst = s_base +
                    (uint32_t)(((nb * BLOCK + r) * C4 + swz(r, lc4)) * 16);
                cp_async16(dst, &x4[(row0 + r) * (T_ / 4) + nc4base + lc4]);
            }
            cp_commit();
            cp_wait<2>();          // tile's own group done; 2 stay in flight
        } else if (tile + 1 < TILES) {
            cp_wait<1>();
        } else {
            cp_wait<0>();
        }
        __syncthreads();           // tile's data visible to all threads

        // ---- sequential scan of this thread's row (conflict-free) ----
        float4* const my = &buf[b][tid][0];
        #pragma unroll
        for (int c4 = 0; c4 < C4; ++c4) {
            float4* const p = &my[c4 ^ myswz];
            const float4 xx = *p;
            float4 sp;
            v += xx.x; sp.x = (v >= thr) ? 1.0f : 0.0f; v = fmaf(-sp.x, thr, v);
            v += xx.y; sp.y = (v >= thr) ? 1.0f : 0.0f; v = fmaf(-sp.y, thr, v);
            v += xx.z; sp.z = (v >= thr) ? 1.0f : 0.0f; v = fmaf(-sp.z, thr, v);
            v += xx.w; sp.w = (v >= thr) ? 1.0f : 0.0f; v = fmaf(-sp.w, thr, v);
            *p = sp;
        }
        __syncthreads();           // spikes of all rows visible

        // ---- coalesced streaming store of spikes ----
        const int c4base = tile * C4;
        #pragma unroll
        for (int k = 0; k < 4; ++k) {
            const int r = lr + k * (BLOCK / 4);
            const float4 f = buf[b][r][swz(r, lc4)];
            __stcs(&sp4[(row0 + r) * (T_ / 4) + c4base + lc4], f);
        }
        __syncthreads();           // buffer b fully drained before reuse
    }

    if (write_vfinal) {
        vfinal[row] = v;
    }
}

extern "C" void kernel_launch(void* const* d_in, const int* in_sizes, int n_in,
                              void* d_out, int out_size) {
    const float* x      = (const float*)d_in[0];
    const float* states = (const float*)d_in[1];
    const float* thr    = (const float*)d_in[2];

    float* out    = (float*)d_out;
    float* spikes = out;
    float* vfin   = out + ROWS * T_;

    const long long need = ROWS * T_ + ROWS;
    const int write_vfinal = ((long long)out_size >= need) ? 1 : 0;

    const int grid = (int)(ROWS / BLOCK);   // 1024
    if_encoder_kernel<<<grid, BLOCK>>>(x, states, thr, spikes, vfin, write_vfinal);
}

// round 5
// speedup vs baseline: 1.5150x; 1.0335x over previous
#include <cuda_runtime.h>
#include <cuda_bf16.h>
#include <cstdint>

// if_encoder: integrate-and-fire with soft reset (bit-exact vs reference scan).
//   d_in[0] input_spikes [B=64, D=4096, T=128] f32 (T contiguous)
//   d_in[1] states       [B, D] f32
//   d_in[2] threshold    scalar f32
//   d_out  = spikes [B, D, T] f32  followed by  v_final [B, D] f32
//
// Warp-autonomous design: each warp owns 32 consecutive rows (one contiguous
// 16KB span of global memory). Every global transaction (cp.async load and
// STG.128 store) moves a full 512B row contiguously -> long DRAM bursts,
// maximal row-buffer locality, no fine-grained read/write interleave.
// Scan: lane = row, smem XOR-swizzled so all LDS/STS.128 are conflict-free.
// No __syncthreads, no mbarriers — only per-warp cp.async groups.

static constexpr int B_ = 64;
static constexpr int D_ = 4096;
static constexpr int T_ = 128;
static constexpr long long ROWS = (long long)B_ * D_;   // 262144
static constexpr int BLOCK = 128;                       // 4 warps
static constexpr int WARPS = BLOCK / 32;
static constexpr int RPW = 32;                          // rows per warp
static constexpr int F4 = T_ / 4;                       // 32 float4 per row
static constexpr int SMEM_BYTES = WARPS * RPW * T_ * 4; // 65536

__device__ __forceinline__ void cp_async16(uint32_t smem_addr, const void* gptr) {
    asm volatile("cp.async.cg.shared.global [%0], [%1], 16;\n"
                 :: "r"(smem_addr), "l"(gptr) : "memory");
}
__device__ __forceinline__ void cp_commit() {
    asm volatile("cp.async.commit_group;\n" ::: "memory");
}
template <int N>
__device__ __forceinline__ void cp_wait() {
    asm volatile("cp.async.wait_group %0;\n" :: "n"(N) : "memory");
}

__global__ __launch_bounds__(BLOCK, 3)
void if_encoder_kernel(const float* __restrict__ x,
                       const float* __restrict__ states,
                       const float* __restrict__ thr_ptr,
                       float* __restrict__ spikes,
                       float* __restrict__ vfinal,
                       int write_vfinal) {
    extern __shared__ __align__(16) float4 smem[];   // [WARPS][RPW][F4]

    const int tid  = threadIdx.x;
    const int wid  = tid >> 5;
    const int lane = tid & 31;

    const long long wrow0 = (long long)blockIdx.x * BLOCK + (long long)wid * RPW;

    const float4* __restrict__ x4  = reinterpret_cast<const float4*>(x);
    float4* __restrict__       sp4 = reinterpret_cast<float4*>(spikes);

    float4* const wbuf = smem + (size_t)wid * RPW * F4;
    const uint32_t sb = (uint32_t)__cvta_generic_to_shared(wbuf);

    // ---- load: 32 full rows, each instruction = 512B contiguous ----
    #pragma unroll
    for (int r = 0; r < RPW; ++r) {
        const int slot = lane ^ (r & 7);                 // swizzle
        const uint32_t dst = sb + (uint32_t)((r * F4 + slot) << 4);
        cp_async16(dst, &x4[(wrow0 + r) * F4 + lane]);
    }
    cp_commit();

    const float thr = thr_ptr[0];
    float v = states[wrow0 + lane];

    cp_wait<0>();
    __syncwarp();

    // ---- sequential scan: lane scans its own row (conflict-free LDS/STS.128) ----
    {
        float4* const my = wbuf + lane * F4;
        const int sw = lane & 7;
        #pragma unroll
        for (int c4 = 0; c4 < F4; ++c4) {
            float4* const p = my + (c4 ^ sw);
            const float4 xx = *p;
            float4 sp;
            v += xx.x; sp.x = (v >= thr) ? 1.0f : 0.0f; v = fmaf(-sp.x, thr, v);
            v += xx.y; sp.y = (v >= thr) ? 1.0f : 0.0f; v = fmaf(-sp.y, thr, v);
            v += xx.z; sp.z = (v >= thr) ? 1.0f : 0.0f; v = fmaf(-sp.z, thr, v);
            v += xx.w; sp.w = (v >= thr) ? 1.0f : 0.0f; v = fmaf(-sp.w, thr, v);
            *p = sp;
        }
    }
    __syncwarp();

    // ---- store: 32 full rows, each instruction = 512B contiguous streaming ----
    #pragma unroll
    for (int r = 0; r < RPW; ++r) {
        const int slot = lane ^ (r & 7);
        const float4 f = wbuf[r * F4 + slot];
        __stcs(&sp4[(wrow0 + r) * F4 + lane], f);
    }

    if (write_vfinal) {
        vfinal[wrow0 + lane] = v;
    }
}

extern "C" void kernel_launch(void* const* d_in, const int* in_sizes, int n_in,
                              void* d_out, int out_size) {
    const float* x      = (const float*)d_in[0];
    const float* states = (const float*)d_in[1];
    const float* thr    = (const float*)d_in[2];

    float* out    = (float*)d_out;
    float* spikes = out;
    float* vfin   = out + ROWS * T_;

    const long long need = ROWS * T_ + ROWS;
    const int write_vfinal = ((long long)out_size >= need) ? 1 : 0;

    static bool attr_set = false;   // idempotent device-state setup (not work)
    if (!attr_set) {
        cudaFuncSetAttribute(if_encoder_kernel,
                             cudaFuncAttributeMaxDynamicSharedMemorySize,
                             SMEM_BYTES);
        attr_set = true;
    }

    const int grid = (int)(ROWS / BLOCK);   // 2048
    if_encoder_kernel<<<grid, BLOCK, SMEM_BYTES>>>(x, states, thr, spikes, vfin,
                                                   write_vfinal);
}